// round 8
// baseline (speedup 1.0000x reference)
#include <cuda_runtime.h>
#include <cuda_fp16.h>
#include <cstdint>
#include <math.h>

#define BATCH 512
#define NNODE 200
#define INC   200
#define HIDC  256
#define NVARS 2

// ---------------- scratch (fp16 hi/lo pairs) -------------------------------
__device__ float  d_mask[NNODE * NNODE];
__device__ __half d_Amh[(size_t)BATCH * NNODE * NNODE];
__device__ __half d_Aml[(size_t)BATCH * NNODE * NNODE];
__device__ __half d_Fh [(size_t)BATCH * NNODE * INC];
__device__ __half d_Fl [(size_t)BATCH * NNODE * INC];
__device__ __half d_W0h[INC * HIDC],  d_W0l[INC * HIDC];
__device__ __half d_W1h[HIDC * HIDC], d_W1l[HIDC * HIDC];
__device__ __half d_W2h[HIDC * HIDC], d_W2l[HIDC * HIDC];
__device__ __half d_Sh [(size_t)BATCH * NNODE * HIDC], d_Sl [(size_t)BATCH * NNODE * HIDC];
__device__ __half d_H1h[(size_t)BATCH * NNODE * HIDC], d_H1l[(size_t)BATCH * NNODE * HIDC];
__device__ __half d_H2h[(size_t)BATCH * NNODE * HIDC], d_H2l[(size_t)BATCH * NNODE * HIDC];

// ---------------- smem stage layout (bytes), BK = 32 ------------------------
#define ST_AHI 0
#define ST_ALO 12288
#define ST_BHI 24576
#define ST_BLO 32768
#define STAGE  40960
#define SMEM_TOTAL (2 * STAGE)   // 81920

// ---------------- asm helpers ----------------------------------------------
__device__ __forceinline__ uint32_t cvta_s(const void* p) {
    uint32_t a;
    asm("{ .reg .u64 t; cvta.to.shared.u64 t, %1; cvt.u32.u64 %0, t; }" : "=r"(a) : "l"(p));
    return a;
}
__device__ __forceinline__ void cpa16(uint32_t dst, const void* src, uint32_t sz) {
    asm volatile("cp.async.cg.shared.global [%0], [%1], 16, %2;"
                 :: "r"(dst), "l"(src), "r"(sz));
}
#define CPA_COMMIT() asm volatile("cp.async.commit_group;" ::: "memory")
#define CPA_WAIT_ALL() asm volatile("cp.async.wait_group 0;" ::: "memory")

__device__ __forceinline__ void ldmx4(uint32_t a, uint32_t* r) {
    asm volatile("ldmatrix.sync.aligned.m8n8.x4.shared.b16 {%0,%1,%2,%3}, [%4];"
                 : "=r"(r[0]), "=r"(r[1]), "=r"(r[2]), "=r"(r[3]) : "r"(a));
}
__device__ __forceinline__ void ldmx4t(uint32_t a, uint32_t* r) {
    asm volatile("ldmatrix.sync.aligned.m8n8.x4.trans.shared.b16 {%0,%1,%2,%3}, [%4];"
                 : "=r"(r[0]), "=r"(r[1]), "=r"(r[2]), "=r"(r[3]) : "r"(a));
}
__device__ __forceinline__ void mma16816(float* c, const uint32_t* a, const uint32_t* b) {
    asm volatile(
        "mma.sync.aligned.m16n8k16.row.col.f32.f16.f16.f32 "
        "{%0,%1,%2,%3}, {%4,%5,%6,%7}, {%8,%9}, {%0,%1,%2,%3};"
        : "+f"(c[0]), "+f"(c[1]), "+f"(c[2]), "+f"(c[3])
        : "r"(a[0]), "r"(a[1]), "r"(a[2]), "r"(a[3]), "r"(b[0]), "r"(b[1]));
}

__device__ __forceinline__ void split2(float a, float b, uint32_t& hi, uint32_t& lo) {
    __half ha = __float2half_rn(a), hb = __float2half_rn(b);
    __half la = __float2half_rn(a - __half2float(ha));
    __half lb = __float2half_rn(b - __half2float(hb));
    hi = (uint32_t)__half_as_ushort(ha) | ((uint32_t)__half_as_ushort(hb) << 16);
    lo = (uint32_t)__half_as_ushort(la) | ((uint32_t)__half_as_ushort(lb) << 16);
}

// one BK=32 stage; term-major j-passes -> RAW distance 8 on each accumulator
__device__ __forceinline__ void mma_stage32(uint32_t st, int warp_m, int warp_n, int lane,
                                            float acc[2][8][4], int mfrags, int ksubs) {
    if (mfrags == 0) return;
#pragma unroll
    for (int s = 0; s < 2; s++) {
        if (s >= ksubs) break;
        uint32_t bhi[8][2], blo[8][2];
        int krow = s * 16 + (lane & 15);
        int csel = (lane >> 4) & 1;
#pragma unroll
        for (int jj = 0; jj < 4; jj++) {
            int cn = (warp_n >> 3) + jj * 2 + csel;
            uint32_t off = (uint32_t)(krow * 256 + ((cn ^ (krow & 7)) << 4));
            uint32_t r[4];
            ldmx4t(st + ST_BHI + off, r);
            bhi[jj*2][0] = r[0]; bhi[jj*2][1] = r[1];
            bhi[jj*2+1][0] = r[2]; bhi[jj*2+1][1] = r[3];
            ldmx4t(st + ST_BLO + off, r);
            blo[jj*2][0] = r[0]; blo[jj*2][1] = r[1];
            blo[jj*2+1][0] = r[2]; blo[jj*2+1][1] = r[3];
        }
#pragma unroll
        for (int i = 0; i < 2; i++) {
            if (i >= mfrags) break;
            uint32_t ao = (uint32_t)(s * 6144 + (warp_m + i * 16 + (lane & 15)) * 48
                                     + ((lane & 16) ? 16 : 0));
            uint32_t ahi[4], alo[4];
            ldmx4(st + ST_AHI + ao, ahi);
            ldmx4(st + ST_ALO + ao, alo);
            // pass 1: hh  (8 independent MMAs)
#pragma unroll
            for (int j = 0; j < 8; j++) mma16816(acc[i][j], ahi, bhi[j]);
            // pass 2: hl
#pragma unroll
            for (int j = 0; j < 8; j++) mma16816(acc[i][j], ahi, blo[j]);
            // pass 3: lh
#pragma unroll
            for (int j = 0; j < 8; j++) mma16816(acc[i][j], alo, bhi[j]);
        }
    }
}

__device__ __forceinline__ void epilogue_hl(__half* __restrict__ Ch, __half* __restrict__ Cl,
                                            int m0, int n0, int warp_m, int warp_n, int lane,
                                            int Mvalid, float acc[2][8][4]) {
    int g = lane >> 2, t = lane & 3;
#pragma unroll
    for (int i = 0; i < 2; i++) {
#pragma unroll
        for (int j = 0; j < 8; j++) {
            int row = m0 + warp_m + i * 16 + g;
            int col = n0 + warp_n + j * 8 + 2 * t;
            if (row < Mvalid) {
                uint32_t h, l;
                split2(acc[i][j][0], acc[i][j][1], h, l);
                *(uint32_t*)&Ch[(size_t)row * HIDC + col] = h;
                *(uint32_t*)&Cl[(size_t)row * HIDC + col] = l;
            }
            if (row + 8 < Mvalid) {
                uint32_t h, l;
                split2(acc[i][j][2], acc[i][j][3], h, l);
                *(uint32_t*)&Ch[(size_t)(row + 8) * HIDC + col] = h;
                *(uint32_t*)&Cl[(size_t)(row + 8) * HIDC + col] = l;
            }
        }
    }
}

// ---------------------------------------------------------------------------
template <bool MGUARD>
__device__ __forceinline__ void gemm_body(
    const __half* __restrict__ Ah, const __half* __restrict__ Al,
    const __half* __restrict__ Bh, const __half* __restrict__ Bl,
    __half* __restrict__ Ch, __half* __restrict__ Cl,
    int K, int Mvalid, int m0, int n0, uint32_t sb0)
{
    int tid = threadIdx.x, lane = tid & 31, wid = tid >> 5;
    int warp_m = (wid >> 1) * 32, warp_n = (wid & 1) * 64;
    int k16max = (K + 15) >> 4;
    int nch = (k16max + 1) >> 1;

    int mfrags = 2;
    if (MGUARD) {
        int rem = Mvalid - m0 - warp_m;
        mfrags = (rem > 16) ? 2 : ((rem > 0) ? 1 : 0);
    }

    float acc[2][8][4];
#pragma unroll
    for (int i = 0; i < 2; i++)
#pragma unroll
        for (int j = 0; j < 8; j++)
#pragma unroll
            for (int q = 0; q < 4; q++) acc[i][j][q] = 0.0f;

    const int arow = tid >> 1, asel = tid & 1;
    const int bkr = tid >> 3, bc0 = (tid & 7) << 1;
    const int gm = m0 + arow;
    const bool mrow_ok = !MGUARD || (gm < Mvalid);

    auto load_stage = [&](int ch, uint32_t st) {
        int kc = ch << 5;
        size_t abase = (size_t)gm * K + kc + asel * 16;
        uint32_t adst = st + asel * 6144 + arow * 48;
#pragma unroll
        for (int q = 0; q < 2; q++) {
            uint32_t sz = (mrow_ok && (kc + asel * 16 + q * 8 < K)) ? 16u : 0u;
            cpa16(adst + ST_AHI + q * 16, Ah + abase + q * 8, sz);
            cpa16(adst + ST_ALO + q * 16, Al + abase + q * 8, sz);
        }
        size_t bbase = (size_t)(kc + bkr) * HIDC + n0;
        uint32_t szb = (kc + bkr < K) ? 16u : 0u;
#pragma unroll
        for (int q = 0; q < 2; q++) {
            int c = bc0 + q;
            uint32_t off = (uint32_t)(bkr * 256 + ((c ^ (bkr & 7)) << 4));
            cpa16(st + ST_BHI + off, Bh + bbase + c * 8, szb);
            cpa16(st + ST_BLO + off, Bl + bbase + c * 8, szb);
        }
    };

    load_stage(0, sb0);
    CPA_COMMIT();

    for (int ch = 0; ch < nch; ch++) {
        CPA_WAIT_ALL();
        __syncthreads();
        if (ch + 1 < nch) {
            load_stage(ch + 1, sb0 + (uint32_t)((ch + 1) & 1) * STAGE);
            CPA_COMMIT();
        }
        int ksubs = k16max - ch * 2;
        if (ksubs > 2) ksubs = 2;
        mma_stage32(sb0 + (uint32_t)(ch & 1) * STAGE, warp_m, warp_n, lane, acc, mfrags, ksubs);
    }

    epilogue_hl(Ch, Cl, m0, n0, warp_m, warp_n, lane, MGUARD ? Mvalid : (1 << 30), acc);
}

// ---------------------------------------------------------------------------
__global__ __launch_bounds__(256, 2) void tc_feat(
    const __half* __restrict__ Ah, const __half* __restrict__ Al,
    const __half* __restrict__ Bh, const __half* __restrict__ Bl,
    __half* __restrict__ Ch, __half* __restrict__ Cl, int K)
{
    extern __shared__ __align__(16) char smem[];
    uint32_t sb0 = cvta_s(smem);
    gemm_body<false>(Ah, Al, Bh, Bl, Ch, Cl, K, 1 << 30,
                     blockIdx.y * 128, blockIdx.x * 128, sb0);
}

__global__ __launch_bounds__(256, 2) void tc_adj(
    const __half* __restrict__ Amh, const __half* __restrict__ Aml,
    const __half* __restrict__ Sh,  const __half* __restrict__ Sl,
    __half* __restrict__ Hh, __half* __restrict__ Hl)
{
    extern __shared__ __align__(16) char smem[];
    uint32_t sb0 = cvta_s(smem);
    int z = blockIdx.z;
    gemm_body<true>(Amh + (size_t)z * NNODE * NNODE, Aml + (size_t)z * NNODE * NNODE,
                    Sh + (size_t)z * NNODE * HIDC,   Sl + (size_t)z * NNODE * HIDC,
                    Hh + (size_t)z * NNODE * HIDC,   Hl + (size_t)z * NNODE * HIDC,
                    NNODE, NNODE, blockIdx.y * 128, blockIdx.x * 128, sb0);
}

// ---------------------------------------------------------------------------
__global__ void mask_kernel(const float* __restrict__ raw) {
    int i = blockIdx.x * blockDim.x + threadIdx.x;
    if (i < NNODE * NNODE) {
        int r = i / NNODE, c = i % NNODE;
        float v = 0.5f * (raw[r * NNODE + c] + raw[c * NNODE + r]);
        if (r == c) v += 1.0f;
        d_mask[i] = v;
    }
}

__device__ __forceinline__ void split4_store(const float* v, __half* Hd, __half* Ld, size_t i4) {
    uint32_t h0, l0, h1, l1;
    split2(v[0], v[1], h0, l0);
    split2(v[2], v[3], h1, l1);
    ((uint2*)Hd)[i4] = make_uint2(h0, h1);
    ((uint2*)Ld)[i4] = make_uint2(l0, l1);
}

#define NA_Q ((size_t)BATCH * NNODE * NNODE / 4)
#define NF_Q ((size_t)BATCH * NNODE * INC / 4)
#define W0_Q (INC * HIDC / 4)
#define W1_Q (HIDC * HIDC / 4)
#define W2_Q (HIDC * HIDC / 4)
#define TOTAL_Q (NA_Q + NF_Q + W0_Q + W1_Q + W2_Q)

__global__ __launch_bounds__(256) void prep_kernel(
    const float* __restrict__ adj, const float* __restrict__ feat,
    const float* __restrict__ W0, const float* __restrict__ W1,
    const float* __restrict__ W2)
{
    size_t gid = (size_t)blockIdx.x * 256 + threadIdx.x;
    if (gid < NA_Q) {
        size_t base = gid * 4;
        int rem = (int)(base % (NNODE * NNODE));
        float4 x = *(const float4*)(adj + base);
        float4 m = *(const float4*)(d_mask + rem);
        float v[4];
        v[0] = m.x / (1.0f + __expf(-x.x));
        v[1] = m.y / (1.0f + __expf(-x.y));
        v[2] = m.z / (1.0f + __expf(-x.z));
        v[3] = m.w / (1.0f + __expf(-x.w));
        split4_store(v, d_Amh, d_Aml, gid);
    } else if (gid < NA_Q + NF_Q) {
        size_t i4 = gid - NA_Q;
        float4 x = *(const float4*)(feat + i4 * 4);
        float v[4] = {x.x, x.y, x.z, x.w};
        split4_store(v, d_Fh, d_Fl, i4);
    } else {
        size_t i = gid - NA_Q - NF_Q;
        const float* src; __half *Hd, *Ld; size_t i4;
        if (i < W0_Q)            { src = W0; Hd = d_W0h; Ld = d_W0l; i4 = i; }
        else if (i < W0_Q + W1_Q){ src = W1; Hd = d_W1h; Ld = d_W1l; i4 = i - W0_Q; }
        else if (i < W0_Q + W1_Q + W2_Q)
                                 { src = W2; Hd = d_W2h; Ld = d_W2l; i4 = i - W0_Q - W1_Q; }
        else return;
        float4 x = *(const float4*)(src + i4 * 4);
        float v[4] = {x.x, x.y, x.z, x.w};
        split4_store(v, Hd, Ld, i4);
    }
}

// ---------------------------------------------------------------------------
__global__ __launch_bounds__(256) void readout_kernel(
    const __half* __restrict__ Hh, const __half* __restrict__ Hl,
    const float* __restrict__ pw, const float* __restrict__ pb,
    float* __restrict__ out)
{
    int b = blockIdx.x;
    int c = threadIdx.x;
    const __half* Hbh = Hh + (size_t)b * NNODE * HIDC;
    const __half* Hbl = Hl + (size_t)b * NNODE * HIDC;

    float s = 0.0f;
    for (int n = 0; n < NNODE; n++)
        s += __half2float(Hbh[n * HIDC + c]) + __half2float(Hbl[n * HIDC + c]);
    s *= (1.0f / NNODE);

    __shared__ float r0[256], r1[256];
    r0[c] = s * pw[c * NVARS + 0];
    r1[c] = s * pw[c * NVARS + 1];
    __syncthreads();
    for (int off = 128; off > 0; off >>= 1) {
        if (c < off) { r0[c] += r0[c + off]; r1[c] += r1[c + off]; }
        __syncthreads();
    }
    if (c == 0) {
        out[b * NVARS + 0] = r0[0] + pb[0];
        out[b * NVARS + 1] = r1[0] + pb[1];
    }
}

// ---------------------------------------------------------------------------
extern "C" void kernel_launch(void* const* d_in, const int* in_sizes, int n_in,
                              void* d_out, int out_size)
{
    const float* adj      = (const float*)d_in[0];
    const float* features = (const float*)d_in[1];
    const float* raw      = (const float*)d_in[2];
    const float* W0       = (const float*)d_in[3];
    const float* W1       = (const float*)d_in[4];
    const float* W2       = (const float*)d_in[5];
    const float* pw       = (const float*)d_in[6];
    const float* pb       = (const float*)d_in[7];
    float* out = (float*)d_out;

    cudaFuncSetAttribute(tc_feat, cudaFuncAttributeMaxDynamicSharedMemorySize, SMEM_TOTAL);
    cudaFuncSetAttribute(tc_adj,  cudaFuncAttributeMaxDynamicSharedMemorySize, SMEM_TOTAL);

    __half *Amh, *Aml, *Fh, *Fl, *W0h, *W0l, *W1h, *W1l, *W2h, *W2l;
    __half *Sh, *Sl, *H1h, *H1l, *H2h, *H2l;
    cudaGetSymbolAddress((void**)&Amh, d_Amh); cudaGetSymbolAddress((void**)&Aml, d_Aml);
    cudaGetSymbolAddress((void**)&Fh, d_Fh);   cudaGetSymbolAddress((void**)&Fl, d_Fl);
    cudaGetSymbolAddress((void**)&W0h, d_W0h); cudaGetSymbolAddress((void**)&W0l, d_W0l);
    cudaGetSymbolAddress((void**)&W1h, d_W1h); cudaGetSymbolAddress((void**)&W1l, d_W1l);
    cudaGetSymbolAddress((void**)&W2h, d_W2h); cudaGetSymbolAddress((void**)&W2l, d_W2l);
    cudaGetSymbolAddress((void**)&Sh, d_Sh);   cudaGetSymbolAddress((void**)&Sl, d_Sl);
    cudaGetSymbolAddress((void**)&H1h, d_H1h); cudaGetSymbolAddress((void**)&H1l, d_H1l);
    cudaGetSymbolAddress((void**)&H2h, d_H2h); cudaGetSymbolAddress((void**)&H2l, d_H2l);

    mask_kernel<<<(NNODE * NNODE + 255) / 256, 256>>>(raw);
    prep_kernel<<<(unsigned)((TOTAL_Q + 255) / 256), 256>>>(adj, features, W0, W1, W2);

    dim3 gF(2, (BATCH * NNODE) / 128);   // (2, 800)
    dim3 gA(2, 2, BATCH);                // (ntile, mtile, batch)

    tc_feat<<<gF, 256, SMEM_TOTAL>>>(Fh, Fl, W0h, W0l, Sh, Sl, INC);
    tc_adj <<<gA, 256, SMEM_TOTAL>>>(Amh, Aml, Sh, Sl, H1h, H1l);

    tc_feat<<<gF, 256, SMEM_TOTAL>>>(H1h, H1l, W1h, W1l, Sh, Sl, HIDC);
    tc_adj <<<gA, 256, SMEM_TOTAL>>>(Amh, Aml, Sh, Sl, H2h, H2l);

    tc_feat<<<gF, 256, SMEM_TOTAL>>>(H2h, H2l, W2h, W2l, Sh, Sl, HIDC);
    tc_adj <<<gA, 256, SMEM_TOTAL>>>(Amh, Aml, Sh, Sl, H1h, H1l);

    readout_kernel<<<BATCH, 256>>>(H1h, H1l, pw, pb, out);
}

// round 9
// speedup vs baseline: 5.0034x; 5.0034x over previous
#include <cuda_runtime.h>
#include <cstdint>
#include <math.h>

#define BATCH 512
#define NNODE 200
#define INC   200
#define HIDC  256
#define NVARS 2
#define NN2   (NNODE * NNODE)   // 40000

// ---------------- scratch ---------------------------------------------------
__device__ float d_mask[NN2];        // (raw+raw^T)/2 + I
__device__ float d_t2[HIDC * NVARS]; // W2 @ pw          [256,2]
__device__ float d_t1[HIDC * NVARS]; // W1 @ t2          [256,2]
__device__ float d_wf[INC  * NVARS]; // W0 @ t1          [200,2]

// ---------------------------------------------------------------------------
// mask = (raw + raw^T) * 0.5 + I
// ---------------------------------------------------------------------------
__global__ void mask_kernel(const float* __restrict__ raw) {
    int i = blockIdx.x * blockDim.x + threadIdx.x;
    if (i < NN2) {
        int r = i / NNODE, c = i % NNODE;
        float v = 0.5f * (raw[r * NNODE + c] + raw[c * NNODE + r]);
        if (r == c) v += 1.0f;
        d_mask[i] = v;
    }
}

// ---------------------------------------------------------------------------
// vout[r][v] = sum_k W[r*K+k] * vin[k][v],  v in {0,1}
// one warp per row, coalesced row reads, shfl reduce.
// grid = ceil(R/8), block = 256 (8 warps)
// ---------------------------------------------------------------------------
__global__ __launch_bounds__(256) void wchain_kernel(
    const float* __restrict__ W, const float* __restrict__ vin,
    float* __restrict__ vout, int R, int K)
{
    int warp = threadIdx.x >> 5, lane = threadIdx.x & 31;
    int r = blockIdx.x * 8 + warp;
    if (r >= R) return;
    float s0 = 0.0f, s1 = 0.0f;
    for (int k = lane; k < K; k += 32) {
        float w = W[(size_t)r * K + k];
        s0 += w * vin[k * NVARS + 0];
        s1 += w * vin[k * NVARS + 1];
    }
#pragma unroll
    for (int off = 16; off > 0; off >>= 1) {
        s0 += __shfl_down_sync(0xFFFFFFFFu, s0, off);
        s1 += __shfl_down_sync(0xFFFFFFFFu, s1, off);
    }
    if (lane == 0) {
        vout[r * NVARS + 0] = s0;
        vout[r * NVARS + 1] = s1;
    }
}

// ---------------------------------------------------------------------------
// sigmoid: adj is binary {0,1} in this dataset -> exact 2-point select;
// exact-equality fallback to full sigmoid keeps general correctness.
// ---------------------------------------------------------------------------
__device__ __forceinline__ float sigv(float x) {
    if (x == 0.0f || x == 1.0f)
        return 0.5f + 0.2310585786300049f * x;   // {sig(0), sig(1)}
    return 1.0f / (1.0f + __expf(-x));
}

// ---------------------------------------------------------------------------
// per-batch collapsed network:
//   A = mask .* sigmoid(adj_b)            (staged in smem, fp32)
//   v1[m] = (1/200) sum_n A[n][m]
//   v2[m] = sum_n v1[n] A[n][m]
//   v3[m] = sum_n v2[n] A[n][m]
//   z[f]  = sum_n v3[n] F_b[n][f]
//   out[b][v] = sum_f z[f] * wf[f][v] + pb[v]
// ---------------------------------------------------------------------------
__global__ __launch_bounds__(256) void collapsed_kernel(
    const float* __restrict__ adj, const float* __restrict__ feat,
    const float* __restrict__ pb, float* __restrict__ out)
{
    extern __shared__ float sA[];           // [NN2] = 160000 bytes
    __shared__ float sv1[NNODE], sv2[NNODE], sv3[NNODE];
    __shared__ float sred[512];

    int tid = threadIdx.x;
    int b = blockIdx.x;

    // stage A_b = mask .* sigmoid(adj_b) into smem (float4, NN2 % 4 == 0)
    const float4* A4 = (const float4*)(adj + (size_t)b * NN2);
    const float4* M4 = (const float4*)d_mask;
    float4* S4 = (float4*)sA;
    for (int i = tid; i < NN2 / 4; i += 256) {
        float4 x = A4[i], m = M4[i], r;
        r.x = m.x * sigv(x.x);
        r.y = m.y * sigv(x.y);
        r.z = m.z * sigv(x.z);
        r.w = m.w * sigv(x.w);
        S4[i] = r;
    }
    __syncthreads();

    // v1 = colsum(A)/200
    if (tid < NNODE) {
        float s0 = 0, s1 = 0, s2 = 0, s3 = 0;
#pragma unroll 4
        for (int n = 0; n < NNODE; n += 4) {
            s0 += sA[(n + 0) * NNODE + tid];
            s1 += sA[(n + 1) * NNODE + tid];
            s2 += sA[(n + 2) * NNODE + tid];
            s3 += sA[(n + 3) * NNODE + tid];
        }
        sv1[tid] = (s0 + s1 + s2 + s3) * (1.0f / NNODE);
    }
    __syncthreads();

    // v2 = v1^T A
    if (tid < NNODE) {
        float s0 = 0, s1 = 0, s2 = 0, s3 = 0;
#pragma unroll 4
        for (int n = 0; n < NNODE; n += 4) {
            s0 += sv1[n + 0] * sA[(n + 0) * NNODE + tid];
            s1 += sv1[n + 1] * sA[(n + 1) * NNODE + tid];
            s2 += sv1[n + 2] * sA[(n + 2) * NNODE + tid];
            s3 += sv1[n + 3] * sA[(n + 3) * NNODE + tid];
        }
        sv2[tid] = s0 + s1 + s2 + s3;
    }
    __syncthreads();

    // v3 = v2^T A
    if (tid < NNODE) {
        float s0 = 0, s1 = 0, s2 = 0, s3 = 0;
#pragma unroll 4
        for (int n = 0; n < NNODE; n += 4) {
            s0 += sv2[n + 0] * sA[(n + 0) * NNODE + tid];
            s1 += sv2[n + 1] * sA[(n + 1) * NNODE + tid];
            s2 += sv2[n + 2] * sA[(n + 2) * NNODE + tid];
            s3 += sv2[n + 3] * sA[(n + 3) * NNODE + tid];
        }
        sv3[tid] = s0 + s1 + s2 + s3;
    }
    __syncthreads();

    // z = v3^T F_b ; partials for out
    float p0 = 0.0f, p1 = 0.0f;
    if (tid < INC) {
        const float* Fb = feat + (size_t)b * NNODE * INC;
        float z0 = 0, z1 = 0, z2 = 0, z3 = 0, z4 = 0, z5 = 0, z6 = 0, z7 = 0;
#pragma unroll 2
        for (int n = 0; n < NNODE; n += 8) {
            z0 += sv3[n + 0] * Fb[(n + 0) * INC + tid];
            z1 += sv3[n + 1] * Fb[(n + 1) * INC + tid];
            z2 += sv3[n + 2] * Fb[(n + 2) * INC + tid];
            z3 += sv3[n + 3] * Fb[(n + 3) * INC + tid];
            z4 += sv3[n + 4] * Fb[(n + 4) * INC + tid];
            z5 += sv3[n + 5] * Fb[(n + 5) * INC + tid];
            z6 += sv3[n + 6] * Fb[(n + 6) * INC + tid];
            z7 += sv3[n + 7] * Fb[(n + 7) * INC + tid];
        }
        float z = ((z0 + z1) + (z2 + z3)) + ((z4 + z5) + (z6 + z7));
        p0 = z * d_wf[tid * NVARS + 0];
        p1 = z * d_wf[tid * NVARS + 1];
    }
    sred[tid] = p0;
    sred[256 + tid] = p1;
    __syncthreads();
#pragma unroll
    for (int off = 128; off > 0; off >>= 1) {
        if (tid < off) {
            sred[tid] += sred[tid + off];
            sred[256 + tid] += sred[256 + tid + off];
        }
        __syncthreads();
    }
    if (tid == 0) {
        out[b * NVARS + 0] = sred[0] + pb[0];
        out[b * NVARS + 1] = sred[256] + pb[1];
    }
}

// ---------------------------------------------------------------------------
extern "C" void kernel_launch(void* const* d_in, const int* in_sizes, int n_in,
                              void* d_out, int out_size)
{
    const float* adj      = (const float*)d_in[0];
    const float* features = (const float*)d_in[1];
    const float* raw      = (const float*)d_in[2];
    const float* W0       = (const float*)d_in[3];
    const float* W1       = (const float*)d_in[4];
    const float* W2       = (const float*)d_in[5];
    const float* pw       = (const float*)d_in[6];
    const float* pb       = (const float*)d_in[7];
    float* out = (float*)d_out;

    const int SMEM_A = NN2 * (int)sizeof(float);   // 160000 B
    cudaFuncSetAttribute(collapsed_kernel,
                         cudaFuncAttributeMaxDynamicSharedMemorySize, SMEM_A);

    float *t2, *t1, *wf;
    cudaGetSymbolAddress((void**)&t2, d_t2);
    cudaGetSymbolAddress((void**)&t1, d_t1);
    cudaGetSymbolAddress((void**)&wf, d_wf);

    // 1. mask
    mask_kernel<<<(NN2 + 255) / 256, 256>>>(raw);

    // 2. fold weight chain: wf = W0 @ (W1 @ (W2 @ pw))   [200,2]
    wchain_kernel<<<(HIDC + 7) / 8, 256>>>(W2, pw, t2, HIDC, HIDC);
    wchain_kernel<<<(HIDC + 7) / 8, 256>>>(W1, t2, t1, HIDC, HIDC);
    wchain_kernel<<<(INC  + 7) / 8, 256>>>(W0, t1, wf, INC,  HIDC);

    // 3. collapsed per-batch network
    collapsed_kernel<<<BATCH, 256, SMEM_A>>>(adj, features, pb, out);
}

// round 10
// speedup vs baseline: 6.0011x; 1.1994x over previous
#include <cuda_runtime.h>
#include <cstdint>
#include <math.h>

#define BATCH 512
#define NNODE 200
#define INC   200
#define HIDC  256
#define NVARS 2
#define NN2   (NNODE * NNODE)   // 40000

// ---------------- scratch ---------------------------------------------------
__device__ float d_mask[NN2];                      // (raw+raw^T)/2 + I
__device__ float d_wf[INC * NVARS];                // W0@W1@W2@pw  [200,2]
__device__ float d_y[(size_t)BATCH * NNODE * NVARS]; // F_b @ wf   [512,200,2]

// ---------------------------------------------------------------------------
// sigmoid: adj is binary {0,1} here -> exact 2-point select; fallback general.
// ---------------------------------------------------------------------------
__device__ __forceinline__ float sigv(float x) {
    if (x == 0.0f || x == 1.0f)
        return 0.5f + 0.2310585786300049f * x;   // {sig(0), sig(1)}
    return 1.0f / (1.0f + __expf(-x));
}

// ---------------------------------------------------------------------------
// prep: blocks 0..62 build mask; block 63 folds wf = W0@(W1@(W2@pw))
// ---------------------------------------------------------------------------
__global__ __launch_bounds__(256) void prep_kernel(
    const float* __restrict__ raw,
    const float* __restrict__ W0, const float* __restrict__ W1,
    const float* __restrict__ W2, const float* __restrict__ pw)
{
    int tid = threadIdx.x;
    if (blockIdx.x < 63) {
        for (int i = blockIdx.x * 256 + tid; i < NN2; i += 63 * 256) {
            int r = i / NNODE, c = i % NNODE;
            float v = 0.5f * (raw[r * NNODE + c] + raw[c * NNODE + r]);
            if (r == c) v += 1.0f;
            d_mask[i] = v;
        }
        return;
    }
    // --- weight chain fold, single block, warp-per-row GEMVs ---
    __shared__ float st2[HIDC * NVARS], st1[HIDC * NVARS];
    int warp = tid >> 5, lane = tid & 31;

    // t2 = W2 @ pw   [256,2]
    for (int r = warp; r < HIDC; r += 8) {
        float s0 = 0, s1 = 0;
        for (int k = lane; k < HIDC; k += 32) {
            float w = W2[(size_t)r * HIDC + k];
            s0 += w * pw[k * NVARS + 0];
            s1 += w * pw[k * NVARS + 1];
        }
#pragma unroll
        for (int off = 16; off > 0; off >>= 1) {
            s0 += __shfl_down_sync(0xFFFFFFFFu, s0, off);
            s1 += __shfl_down_sync(0xFFFFFFFFu, s1, off);
        }
        if (lane == 0) { st2[r * 2] = s0; st2[r * 2 + 1] = s1; }
    }
    __syncthreads();
    // t1 = W1 @ t2   [256,2]
    for (int r = warp; r < HIDC; r += 8) {
        float s0 = 0, s1 = 0;
        for (int k = lane; k < HIDC; k += 32) {
            float w = W1[(size_t)r * HIDC + k];
            s0 += w * st2[k * 2]; s1 += w * st2[k * 2 + 1];
        }
#pragma unroll
        for (int off = 16; off > 0; off >>= 1) {
            s0 += __shfl_down_sync(0xFFFFFFFFu, s0, off);
            s1 += __shfl_down_sync(0xFFFFFFFFu, s1, off);
        }
        if (lane == 0) { st1[r * 2] = s0; st1[r * 2 + 1] = s1; }
    }
    __syncthreads();
    // wf = W0 @ t1   [200,2]
    for (int r = warp; r < INC; r += 8) {
        float s0 = 0, s1 = 0;
        for (int k = lane; k < HIDC; k += 32) {
            float w = W0[(size_t)r * HIDC + k];
            s0 += w * st1[k * 2]; s1 += w * st1[k * 2 + 1];
        }
#pragma unroll
        for (int off = 16; off > 0; off >>= 1) {
            s0 += __shfl_down_sync(0xFFFFFFFFu, s0, off);
            s1 += __shfl_down_sync(0xFFFFFFFFu, s1, off);
        }
        if (lane == 0) { d_wf[r * 2] = s0; d_wf[r * 2 + 1] = s1; }
    }
}

// ---------------------------------------------------------------------------
// y[row][v] = sum_f F[row][f] * wf[f][v]   (row = b*200+n, streams 82MB)
// warp per row, 8 rows per block.
// ---------------------------------------------------------------------------
__global__ __launch_bounds__(256) void y_kernel(const float* __restrict__ feat)
{
    __shared__ float swf0[INC], swf1[INC];
    int tid = threadIdx.x, warp = tid >> 5, lane = tid & 31;
    if (tid < INC) { swf0[tid] = d_wf[tid * 2]; swf1[tid] = d_wf[tid * 2 + 1]; }
    __syncthreads();

    int row = blockIdx.x * 8 + warp;   // < 102400
    const float* Fr = feat + (size_t)row * INC;
    float s0 = 0, s1 = 0, t0 = 0, t1 = 0;
    for (int k = lane; k < INC; k += 64) {
        float f = Fr[k];
        s0 += f * swf0[k]; s1 += f * swf1[k];
        int k2 = k + 32;
        if (k2 < INC) {
            float g = Fr[k2];
            t0 += g * swf0[k2]; t1 += g * swf1[k2];
        }
    }
    s0 += t0; s1 += t1;
#pragma unroll
    for (int off = 16; off > 0; off >>= 1) {
        s0 += __shfl_down_sync(0xFFFFFFFFu, s0, off);
        s1 += __shfl_down_sync(0xFFFFFFFFu, s1, off);
    }
    if (lane == 0) { d_y[row * 2] = s0; d_y[row * 2 + 1] = s1; }
}

// ---------------------------------------------------------------------------
// per-batch adjacency chain + combine:
//   A = mask .* sigmoid(adj_b)  (smem, 160KB)
//   v1 = colsum(A)/200; v2 = v1^T A; v3 = v2^T A
//   out[b][v] = sum_n v3[n] * y[b][n][v] + pb[v]
// 1024 threads: staging MLP-rich; sweeps 4 row-chunks x 200 cols.
// ---------------------------------------------------------------------------
__global__ __launch_bounds__(1024, 1) void adj_kernel(
    const float* __restrict__ adj, const float* __restrict__ pb,
    float* __restrict__ out)
{
    extern __shared__ float sA[];                 // [NN2] 160000 B
    __shared__ float spart[1024];                 // 4 x 256 partials / reduce
    __shared__ float sv1[NNODE], sv2[NNODE], sv3[NNODE];

    int tid = threadIdx.x;
    int b = blockIdx.x;

    // ---- stage A = mask .* sigv(adj_b), unroll 5 for MLP ----
    const float4* A4 = (const float4*)(adj + (size_t)b * NN2);
    const float4* M4 = (const float4*)d_mask;
    float4* S4 = (float4*)sA;
    const int Q4 = NN2 / 4;                       // 10000
#pragma unroll 1
    for (int base = 0; base < Q4; base += 5 * 1024) {
        float4 xa[5], xm[5];
#pragma unroll
        for (int q = 0; q < 5; q++) {
            int i = base + tid + q * 1024;
            if (i < Q4) { xa[q] = A4[i]; xm[q] = M4[i]; }
        }
#pragma unroll
        for (int q = 0; q < 5; q++) {
            int i = base + tid + q * 1024;
            if (i < Q4) {
                float4 r;
                r.x = xm[q].x * sigv(xa[q].x);
                r.y = xm[q].y * sigv(xa[q].y);
                r.z = xm[q].z * sigv(xa[q].z);
                r.w = xm[q].w * sigv(xa[q].w);
                S4[i] = r;
            }
        }
    }
    __syncthreads();

    const int g = tid >> 8;         // row-chunk 0..3 (50 rows each)
    const int col = tid & 255;      // 0..255 (<200 active)
    const int n0 = g * 50;

    // ---- v1 = colsum/200 ----
    {
        float s = 0;
        if (col < NNODE) {
#pragma unroll 10
            for (int n = 0; n < 50; n++) s += sA[(n0 + n) * NNODE + col];
        }
        spart[(g << 8) + col] = s;
        __syncthreads();
        if (tid < NNODE)
            sv1[tid] = (spart[tid] + spart[256 + tid] + spart[512 + tid] + spart[768 + tid])
                       * (1.0f / NNODE);
        __syncthreads();
    }
    // ---- v2 = v1^T A ----
    {
        float s = 0;
        if (col < NNODE) {
#pragma unroll 10
            for (int n = 0; n < 50; n++) s += sv1[n0 + n] * sA[(n0 + n) * NNODE + col];
        }
        spart[(g << 8) + col] = s;
        __syncthreads();
        if (tid < NNODE)
            sv2[tid] = spart[tid] + spart[256 + tid] + spart[512 + tid] + spart[768 + tid];
        __syncthreads();
    }
    // ---- v3 = v2^T A ----
    {
        float s = 0;
        if (col < NNODE) {
#pragma unroll 10
            for (int n = 0; n < 50; n++) s += sv2[n0 + n] * sA[(n0 + n) * NNODE + col];
        }
        spart[(g << 8) + col] = s;
        __syncthreads();
        if (tid < NNODE)
            sv3[tid] = spart[tid] + spart[256 + tid] + spart[512 + tid] + spart[768 + tid];
        __syncthreads();
    }

    // ---- combine with y ----
    float p0 = 0, p1 = 0;
    if (tid < NNODE) {
        float2 yv = ((const float2*)d_y)[b * NNODE + tid];
        p0 = sv3[tid] * yv.x;
        p1 = sv3[tid] * yv.y;
    }
    if (tid < 256) { spart[tid] = p0; spart[256 + tid] = p1; }
    __syncthreads();
#pragma unroll
    for (int off = 128; off > 0; off >>= 1) {
        if (tid < off) {
            spart[tid] += spart[tid + off];
            spart[256 + tid] += spart[256 + tid + off];
        }
        __syncthreads();
    }
    if (tid == 0) {
        out[b * NVARS + 0] = spart[0] + pb[0];
        out[b * NVARS + 1] = spart[256] + pb[1];
    }
}

// ---------------------------------------------------------------------------
extern "C" void kernel_launch(void* const* d_in, const int* in_sizes, int n_in,
                              void* d_out, int out_size)
{
    const float* adj      = (const float*)d_in[0];
    const float* features = (const float*)d_in[1];
    const float* raw      = (const float*)d_in[2];
    const float* W0       = (const float*)d_in[3];
    const float* W1       = (const float*)d_in[4];
    const float* W2       = (const float*)d_in[5];
    const float* pw       = (const float*)d_in[6];
    const float* pb       = (const float*)d_in[7];
    float* out = (float*)d_out;

    const int SMEM_A = NN2 * (int)sizeof(float);   // 160000 B
    cudaFuncSetAttribute(adj_kernel,
                         cudaFuncAttributeMaxDynamicSharedMemorySize, SMEM_A);

    // 1. mask + weight-chain fold (one kernel)
    prep_kernel<<<64, 256>>>(raw, W0, W1, W2, pw);
    // 2. y = F @ wf  (streams features at full BW)
    y_kernel<<<(BATCH * NNODE) / 8, 256>>>(features);
    // 3. adjacency chain + combine
    adj_kernel<<<BATCH, 1024, SMEM_A>>>(adj, pb, out);
}

// round 11
// speedup vs baseline: 10.9520x; 1.8250x over previous
#include <cuda_runtime.h>
#include <cstdint>
#include <math.h>

#define BATCH 512
#define NNODE 200
#define INC   200
#define HIDC  256
#define NVARS 2
#define NN2   (NNODE * NNODE)   // 40000

// ---------------- scratch ---------------------------------------------------
__device__ float d_mask[NN2];                        // (raw+raw^T)/2 + I
__device__ float d_t2[HIDC * NVARS];                 // W2 @ pw
__device__ float d_t1[HIDC * NVARS];                 // W1 @ t2
__device__ float d_wf[INC * NVARS];                  // W0 @ t1   [200,2]
__device__ float d_y[(size_t)BATCH * NNODE * NVARS]; // F_b @ wf  [512,200,2]

// ---------------------------------------------------------------------------
__device__ __forceinline__ float sigv(float x) {
    if (x == 0.0f || x == 1.0f)
        return 0.5f + 0.2310585786300049f * x;   // {sig(0), sig(1)} exact
    return 1.0f / (1.0f + __expf(-x));
}

// ---------------------------------------------------------------------------
// mask = (raw + raw^T)*0.5 + I
// ---------------------------------------------------------------------------
__global__ __launch_bounds__(256) void mask_kernel(const float* __restrict__ raw) {
    int i = blockIdx.x * 256 + threadIdx.x;
    if (i < NN2) {
        int r = i / NNODE, c = i % NNODE;
        float v = 0.5f * (raw[r * NNODE + c] + raw[c * NNODE + r]);
        if (r == c) v += 1.0f;
        d_mask[i] = v;
    }
}

// ---------------------------------------------------------------------------
// vout[r][v] = sum_k W[r*K+k] * vin[k][v]; warp per row, 4 warps/block.
// ---------------------------------------------------------------------------
__global__ __launch_bounds__(128) void wchain_kernel(
    const float* __restrict__ W, const float* __restrict__ vin,
    float* __restrict__ vout, int R, int K)
{
    int warp = threadIdx.x >> 5, lane = threadIdx.x & 31;
    int r = blockIdx.x * 4 + warp;
    if (r >= R) return;
    float s0 = 0.0f, s1 = 0.0f;
    for (int k = lane; k < K; k += 32) {
        float w = W[(size_t)r * K + k];
        s0 += w * vin[k * NVARS + 0];
        s1 += w * vin[k * NVARS + 1];
    }
#pragma unroll
    for (int off = 16; off > 0; off >>= 1) {
        s0 += __shfl_down_sync(0xFFFFFFFFu, s0, off);
        s1 += __shfl_down_sync(0xFFFFFFFFu, s1, off);
    }
    if (lane == 0) {
        vout[r * NVARS + 0] = s0;
        vout[r * NVARS + 1] = s1;
    }
}

// ---------------------------------------------------------------------------
// y[row][v] = sum_f F[row][f] * wf[f][v]; warp per row, 8 rows/block.
// ---------------------------------------------------------------------------
__global__ __launch_bounds__(256) void y_kernel(const float* __restrict__ feat)
{
    __shared__ float swf0[INC], swf1[INC];
    int tid = threadIdx.x, warp = tid >> 5, lane = tid & 31;
    if (tid < INC) { swf0[tid] = d_wf[tid * 2]; swf1[tid] = d_wf[tid * 2 + 1]; }
    __syncthreads();

    int row = blockIdx.x * 8 + warp;   // < 102400
    const float* Fr = feat + (size_t)row * INC;
    float s0 = 0, s1 = 0, t0 = 0, t1 = 0;
    for (int k = lane; k < INC; k += 64) {
        float f = Fr[k];
        s0 += f * swf0[k]; s1 += f * swf1[k];
        int k2 = k + 32;
        if (k2 < INC) {
            float g = Fr[k2];
            t0 += g * swf0[k2]; t1 += g * swf1[k2];
        }
    }
    s0 += t0; s1 += t1;
#pragma unroll
    for (int off = 16; off > 0; off >>= 1) {
        s0 += __shfl_down_sync(0xFFFFFFFFu, s0, off);
        s1 += __shfl_down_sync(0xFFFFFFFFu, s1, off);
    }
    if (lane == 0) { d_y[row * 2] = s0; d_y[row * 2 + 1] = s1; }
}

// ---------------------------------------------------------------------------
// per-batch adjacency chain + combine (unchanged from round 10)
// ---------------------------------------------------------------------------
__global__ __launch_bounds__(1024, 1) void adj_kernel(
    const float* __restrict__ adj, const float* __restrict__ pb,
    float* __restrict__ out)
{
    extern __shared__ float sA[];                 // [NN2] 160000 B
    __shared__ float spart[1024];
    __shared__ float sv1[NNODE], sv2[NNODE], sv3[NNODE];

    int tid = threadIdx.x;
    int b = blockIdx.x;

    const float4* A4 = (const float4*)(adj + (size_t)b * NN2);
    const float4* M4 = (const float4*)d_mask;
    float4* S4 = (float4*)sA;
    const int Q4 = NN2 / 4;                       // 10000
#pragma unroll 1
    for (int base = 0; base < Q4; base += 5 * 1024) {
        float4 xa[5], xm[5];
#pragma unroll
        for (int q = 0; q < 5; q++) {
            int i = base + tid + q * 1024;
            if (i < Q4) { xa[q] = A4[i]; xm[q] = M4[i]; }
        }
#pragma unroll
        for (int q = 0; q < 5; q++) {
            int i = base + tid + q * 1024;
            if (i < Q4) {
                float4 r;
                r.x = xm[q].x * sigv(xa[q].x);
                r.y = xm[q].y * sigv(xa[q].y);
                r.z = xm[q].z * sigv(xa[q].z);
                r.w = xm[q].w * sigv(xa[q].w);
                S4[i] = r;
            }
        }
    }
    __syncthreads();

    const int g = tid >> 8;         // row-chunk 0..3 (50 rows each)
    const int col = tid & 255;
    const int n0 = g * 50;

    {
        float s = 0;
        if (col < NNODE) {
#pragma unroll 10
            for (int n = 0; n < 50; n++) s += sA[(n0 + n) * NNODE + col];
        }
        spart[(g << 8) + col] = s;
        __syncthreads();
        if (tid < NNODE)
            sv1[tid] = (spart[tid] + spart[256 + tid] + spart[512 + tid] + spart[768 + tid])
                       * (1.0f / NNODE);
        __syncthreads();
    }
    {
        float s = 0;
        if (col < NNODE) {
#pragma unroll 10
            for (int n = 0; n < 50; n++) s += sv1[n0 + n] * sA[(n0 + n) * NNODE + col];
        }
        spart[(g << 8) + col] = s;
        __syncthreads();
        if (tid < NNODE)
            sv2[tid] = spart[tid] + spart[256 + tid] + spart[512 + tid] + spart[768 + tid];
        __syncthreads();
    }
    {
        float s = 0;
        if (col < NNODE) {
#pragma unroll 10
            for (int n = 0; n < 50; n++) s += sv2[n0 + n] * sA[(n0 + n) * NNODE + col];
        }
        spart[(g << 8) + col] = s;
        __syncthreads();
        if (tid < NNODE)
            sv3[tid] = spart[tid] + spart[256 + tid] + spart[512 + tid] + spart[768 + tid];
        __syncthreads();
    }

    float p0 = 0, p1 = 0;
    if (tid < NNODE) {
        float2 yv = ((const float2*)d_y)[b * NNODE + tid];
        p0 = sv3[tid] * yv.x;
        p1 = sv3[tid] * yv.y;
    }
    if (tid < 256) { spart[tid] = p0; spart[256 + tid] = p1; }
    __syncthreads();
#pragma unroll
    for (int off = 128; off > 0; off >>= 1) {
        if (tid < off) {
            spart[tid] += spart[tid + off];
            spart[256 + tid] += spart[256 + tid + off];
        }
        __syncthreads();
    }
    if (tid == 0) {
        out[b * NVARS + 0] = spart[0] + pb[0];
        out[b * NVARS + 1] = spart[256] + pb[1];
    }
}

// ---------------------------------------------------------------------------
extern "C" void kernel_launch(void* const* d_in, const int* in_sizes, int n_in,
                              void* d_out, int out_size)
{
    const float* adj      = (const float*)d_in[0];
    const float* features = (const float*)d_in[1];
    const float* raw      = (const float*)d_in[2];
    const float* W0       = (const float*)d_in[3];
    const float* W1       = (const float*)d_in[4];
    const float* W2       = (const float*)d_in[5];
    const float* pw       = (const float*)d_in[6];
    const float* pb       = (const float*)d_in[7];
    float* out = (float*)d_out;

    const int SMEM_A = NN2 * (int)sizeof(float);   // 160000 B
    cudaFuncSetAttribute(adj_kernel,
                         cudaFuncAttributeMaxDynamicSharedMemorySize, SMEM_A);

    float *t2, *t1, *wf;
    cudaGetSymbolAddress((void**)&t2, d_t2);
    cudaGetSymbolAddress((void**)&t1, d_t1);
    cudaGetSymbolAddress((void**)&wf, d_wf);

    // prep: mask + grid-parallel weight-chain fold
    mask_kernel<<<(NN2 + 255) / 256, 256>>>(raw);
    wchain_kernel<<<(HIDC + 3) / 4, 128>>>(W2, pw, t2, HIDC, HIDC);
    wchain_kernel<<<(HIDC + 3) / 4, 128>>>(W1, t2, t1, HIDC, HIDC);
    wchain_kernel<<<(INC  + 3) / 4, 128>>>(W0, t1, wf, INC,  HIDC);

    // y = F @ wf  (streams 82MB)
    y_kernel<<<(BATCH * NNODE) / 8, 256>>>(features);
    // adjacency chain + combine (streams 82MB)
    adj_kernel<<<BATCH, 1024, SMEM_A>>>(adj, pb, out);
}